// round 14
// baseline (speedup 1.0000x reference)
#include <cuda_runtime.h>
#include <cuda_bf16.h>
#include <cstdint>

// ---------------------------------------------------------------------------
// Problem constants (fixed instance: B=2048 windows, N_actual=60, C=512)
// ---------------------------------------------------------------------------
#define N_ACT    60
#define CDIM     512
#define NHEAD    16
#define HD       32
#define BWIN     2048
#define MROWS    (BWIN * N_ACT)          // 122880 = 480 * 256
#define SCALE_Q  0.1767766952966369f     // 32^-0.5

// ---------------------------------------------------------------------------
// Device scratch (static __device__ arrays: allocation-guard safe).
// K-dimension data (g_x cols, g_qkvT cols, g_projT cols, attn-O cols of
// g_qkv) is stored PERM-8: within each 8-col group, order [0,4,1,5,2,6,3,7].
// q/k/v n-cols of g_qkv are logical (k_attn consumes them logically).
// ---------------------------------------------------------------------------
__device__ float g_qkvT[3 * CDIM * CDIM];            // [1536][512] W^T tf32, perm-8 cols
__device__ float g_projT[CDIM * CDIM];               // [512][512]  W^T tf32, perm-8 cols
__device__ float g_x[(size_t)MROWS * CDIM];          // [122880][512] x tf32, perm-8 cols
__device__ float g_qkv[(size_t)MROWS * 3 * CDIM];    // [122880][1536]

// ---------------------------------------------------------------------------
// Helpers
// ---------------------------------------------------------------------------
__device__ __forceinline__ float tf32r(float x) {
    float y;
    asm("cvt.rna.tf32.f32 %0, %1;" : "=f"(y) : "f"(x));
    return y;
}
__device__ __forceinline__ uint32_t f2u(float x) { return __float_as_uint(x); }

__device__ __forceinline__ void mma_tf32(float c[4],
                                         float a0, float a1, float a2, float a3,
                                         float b0, float b1) {
    asm volatile(
        "mma.sync.aligned.m16n8k8.row.col.f32.tf32.tf32.f32 "
        "{%0,%1,%2,%3}, {%4,%5,%6,%7}, {%8,%9}, {%0,%1,%2,%3};\n"
        : "+f"(c[0]), "+f"(c[1]), "+f"(c[2]), "+f"(c[3])
        : "r"(f2u(a0)), "r"(f2u(a1)), "r"(f2u(a2)), "r"(f2u(a3)),
          "r"(f2u(b0)), "r"(f2u(b1)));
}

__device__ __forceinline__ uint32_t smem_u32(const void* p) {
    uint32_t a;
    asm("{ .reg .u64 t; cvta.to.shared.u64 t, %1; cvt.u32.u64 %0, t; }"
        : "=r"(a) : "l"(p));
    return a;
}

__device__ __forceinline__ void cpa16(uint32_t smem_dst, const float* gsrc) {
    asm volatile("cp.async.cg.shared.global [%0], [%1], 16;"
                 :: "r"(smem_dst), "l"(gsrc));
}
#define CPA_COMMIT() asm volatile("cp.async.commit_group;" ::: "memory")
#define CPA_WAIT0()  asm volatile("cp.async.wait_group 0;" ::: "memory")

// ---------------------------------------------------------------------------
// Kernel: tf32-round x + perm-8 columns -> g_x. 8 floats per thread.
// perm-8 pack of 8 logical floats [c0..c7]: out = {c0,c4,c1,c5, c2,c6,c3,c7}
// ---------------------------------------------------------------------------
__global__ void kround(const float* __restrict__ src) {
    size_t i = ((size_t)blockIdx.x * 256 + threadIdx.x) * 8;
    float4 v0 = *reinterpret_cast<const float4*>(src + i);
    float4 v1 = *reinterpret_cast<const float4*>(src + i + 4);
    float4 o0 = make_float4(tf32r(v0.x), tf32r(v1.x), tf32r(v0.y), tf32r(v1.y));
    float4 o1 = make_float4(tf32r(v0.z), tf32r(v1.z), tf32r(v0.w), tf32r(v1.w));
    *reinterpret_cast<float4*>(g_x + i)     = o0;
    *reinterpret_cast<float4*>(g_x + i + 4) = o1;
}

// ---------------------------------------------------------------------------
// Kernel 0: transpose + tf32-round weights, perm-8 the k columns.
// which==0: qkv_w [512][1536] -> g_qkvT[1536][512]
// which==1: proj_w [512][512] -> g_projT[512][512]
// dst[n][perm(k)] = tf32r(src[k][n])
// ---------------------------------------------------------------------------
__global__ void ktranspose(const float* __restrict__ src, int R, int Ccols, int which) {
    __shared__ float tile[32][33];
    float* dst = which ? g_projT : g_qkvT;
    int cb = blockIdx.x * 32, rb = blockIdx.y * 32;
    tile[threadIdx.y][threadIdx.x] = src[(size_t)(rb + threadIdx.y) * Ccols + cb + threadIdx.x];
    __syncthreads();
    int tx = threadIdx.x;                                 // k within 32-group
    int px = (tx & 24) + (tx & 3) * 2 + ((tx >> 2) & 1);  // perm-8
    dst[(size_t)(cb + threadIdx.y) * R + rb + px] = tf32r(tile[threadIdx.x][threadIdx.y]);
}

// ---------------------------------------------------------------------------
// cp.async double-buffered tf32 GEMM.
// CTA tile 256(m) x 128(n), 256 threads (8 warps = 4m x 2n), warp tile 64x64.
// K-chunk 8, 64 chunks, 2 smem stages, rows of 8 floats (32 B), no padding
// (perm-8 already in gmem). Static smem: 2*(256+128)*8*4 = 24576 B.
// Fragment loads: LDS.64, 2-phase conflict-free.
// mode 0: A=g_x (lda 512),  B=g_qkvT, bias=qkvb, C=g_qkv (ldc 1536),
//         q-cols scaled, output tf32-rounded (logical n-cols).
// mode 1: A=g_qkv (lda 1536, attn-O in cols 0..511, perm-8 + tf32),
//         B=g_projT, bias=projb, C=out (ldc 512).
// ---------------------------------------------------------------------------
#define KC 8

__global__ __launch_bounds__(256, 1) void kgemm_ca(const float* __restrict__ qkvb,
                                                   const float* __restrict__ projb,
                                                   float* __restrict__ out,
                                                   int mode) {
    __shared__ __align__(16) float sA[2][256 * KC];
    __shared__ __align__(16) float sB[2][128 * KC];

    const float* Aptr = mode ? g_qkv : g_x;
    const int    lda  = mode ? (3 * CDIM) : CDIM;
    const float* Bw   = mode ? g_projT : g_qkvT;
    const float* bias = mode ? projb : qkvb;
    float*       Cp   = mode ? out : g_qkv;
    const int    ldc  = mode ? CDIM : (3 * CDIM);

    const int m0 = blockIdx.y * 256;
    const int n0 = blockIdx.x * 128;
    const int tid  = threadIdx.x;
    const int lane = tid & 31;
    const int warp = tid >> 5;
    const int g = lane >> 2, t = lane & 3;
    const int wm = warp & 3;       // 4 m-stripes of 64 rows
    const int wn = warp >> 2;      // 2 n-stripes of 64 cols

    // staging: A row = tid (32 B per chunk); B row = tid>>1, 16B half = tid&1
    const float* aG = Aptr + (size_t)(m0 + tid) * lda;
    const float* bG = Bw + (size_t)(n0 + (tid >> 1)) * CDIM + (tid & 1) * 4;
    const uint32_t aS = smem_u32(&sA[0][tid * KC]);
    const uint32_t bS = smem_u32(&sB[0][(tid >> 1) * KC + (tid & 1) * 4]);
    const uint32_t stgA = 256 * KC * 4;   // bytes per A stage
    const uint32_t stgB = 128 * KC * 4;   // bytes per B stage

    float acc[4][8][4];
    #pragma unroll
    for (int im = 0; im < 4; im++)
        #pragma unroll
        for (int jn = 0; jn < 8; jn++)
            #pragma unroll
            for (int q = 0; q < 4; q++) acc[im][jn][q] = 0.f;

    // prologue: stage chunk 0 into stage 0
    cpa16(aS, aG);
    cpa16(aS + 16, aG + 4);
    cpa16(bS, bG);
    CPA_COMMIT();

    for (int kc = 0; kc < 64; kc++) {
        CPA_WAIT0();            // current chunk resident
        __syncthreads();        // all warps done with the other stage

        // issue chunk kc+1 into the other stage (overlaps compute below)
        if (kc < 63) {
            const uint32_t so = ((kc + 1) & 1) ? stgA : 0u;
            const uint32_t sb = ((kc + 1) & 1) ? stgB : 0u;
            const int ko = (kc + 1) * KC;
            cpa16(aS + so, aG + ko);
            cpa16(aS + so + 16, aG + ko + 4);
            cpa16(bS + sb, bG + ko);
            CPA_COMMIT();
        }

        // compute on current stage: 32 mmas per warp
        const int cur = kc & 1;
        const float* cA = &sA[cur][(wm * 64 + g) * KC + 2 * t];
        const float* cB = &sB[cur][(wn * 64 + g) * KC + 2 * t];
        float2 av[4][2];
        #pragma unroll
        for (int im = 0; im < 4; im++) {
            av[im][0] = *reinterpret_cast<const float2*>(cA + im * 16 * KC);
            av[im][1] = *reinterpret_cast<const float2*>(cA + im * 16 * KC + 8 * KC);
        }
        float2 bv[8];
        #pragma unroll
        for (int jn = 0; jn < 8; jn++)
            bv[jn] = *reinterpret_cast<const float2*>(cB + jn * 8 * KC);
        #pragma unroll
        for (int im = 0; im < 4; im++)
            #pragma unroll
            for (int jn = 0; jn < 8; jn++)
                mma_tf32(acc[im][jn],
                         av[im][0].x, av[im][1].x, av[im][0].y, av[im][1].y,
                         bv[jn].x, bv[jn].y);
    }

    // ---- epilogue: bias (+ q-scale / tf32 round for mode 0), float2 stores --
    #pragma unroll
    for (int im = 0; im < 4; im++) {
        #pragma unroll
        for (int jn = 0; jn < 8; jn++) {
            #pragma unroll
            for (int h = 0; h < 2; h++) {      // q pairs (0,1) and (2,3)
                const int row = m0 + wm * 64 + im * 16 + g + h * 8;
                const int col = n0 + wn * 64 + jn * 8 + 2 * t;
                float v0 = acc[im][jn][2 * h + 0] + bias[col];
                float v1 = acc[im][jn][2 * h + 1] + bias[col + 1];
                if (mode == 0) {
                    if (col < CDIM) { v0 *= SCALE_Q; v1 *= SCALE_Q; }
                    v0 = tf32r(v0); v1 = tf32r(v1);
                }
                *reinterpret_cast<float2*>(Cp + (size_t)row * ldc + col) =
                    make_float2(v0, v1);
            }
        }
    }
}

// ---------------------------------------------------------------------------
// Attention kernel: one CTA per (window, head). 128 threads (4 warps).
// smem: sU holds q|k (2 x 64x40) then is reused for P (64x72); svT (32x72).
// 29.75 KB. Reads q/k/v at LOGICAL cols; writes O tf32-rounded at PERM-8
// cols (it is the proj GEMM's A operand).
// ---------------------------------------------------------------------------
__global__ __launch_bounds__(128) void k_attn() {
    __shared__ float sU[5120];
    __shared__ float svT[32 * 72];

    float* sq = sU;
    float* sk = sU + 2560;
    float* sS = sU;

    const int b = blockIdx.x;
    const int h = blockIdx.y;
    const int tid  = threadIdx.x;
    const int lane = tid & 31;
    const int warp = tid >> 5;
    const int g = lane >> 2, t = lane & 3;

    const float* qb = g_qkv + (size_t)b * N_ACT * (3 * CDIM) + h * HD;
    const float* kb = qb + CDIM;
    const float* vb = qb + 2 * CDIM;

    for (int i = tid; i < 64 * 8; i += 128) {
        int r = i >> 3, c4 = i & 7, cb = c4 * 4;
        float4 vq, vk, vv;
        if (r < N_ACT) {
            vq = *reinterpret_cast<const float4*>(qb + (size_t)r * (3 * CDIM) + cb);
            vk = *reinterpret_cast<const float4*>(kb + (size_t)r * (3 * CDIM) + cb);
            vv = *reinterpret_cast<const float4*>(vb + (size_t)r * (3 * CDIM) + cb);
        } else {
            vq = vk = vv = make_float4(0.f, 0.f, 0.f, 0.f);
        }
        int base = r * 40 + (cb & 24) + ((cb >> 2) & 1);
        sq[base + 0] = vq.x; sq[base + 2] = vq.y; sq[base + 4] = vq.z; sq[base + 6] = vq.w;
        sk[base + 0] = vk.x; sk[base + 2] = vk.y; sk[base + 4] = vk.z; sk[base + 6] = vk.w;
        int pr = (r & 56) + (r & 3) * 2 + ((r >> 2) & 1);   // permuted token pos
        svT[(cb + 0) * 72 + pr] = vv.x;
        svT[(cb + 1) * 72 + pr] = vv.y;
        svT[(cb + 2) * 72 + pr] = vv.z;
        svT[(cb + 3) * 72 + pr] = vv.w;
    }
    __syncthreads();

    float sacc[8][4];
    #pragma unroll
    for (int jn = 0; jn < 8; jn++)
        #pragma unroll
        for (int q = 0; q < 4; q++) sacc[jn][q] = 0.f;

    #pragma unroll
    for (int ks = 0; ks < 4; ks++) {
        const int k0 = ks * 8 + 2 * t;
        const float* ap = sq + (16 * warp + g) * 40 + k0;
        float2 a0 = *reinterpret_cast<const float2*>(ap);
        float2 a1 = *reinterpret_cast<const float2*>(ap + 8 * 40);
        #pragma unroll
        for (int jn = 0; jn < 8; jn++) {
            float2 bp = *reinterpret_cast<const float2*>(sk + (jn * 8 + g) * 40 + k0);
            mma_tf32(sacc[jn], a0.x, a1.x, a0.y, a1.y, bp.x, bp.y);
        }
    }

    float mx[2] = {-1e30f, -1e30f};
    #pragma unroll
    for (int jn = 0; jn < 8; jn++)
        #pragma unroll
        for (int q = 0; q < 4; q++) {
            int col = jn * 8 + 2 * t + (q & 1);
            float v = sacc[jn][q] + (col >= N_ACT ? -1e9f : 0.f);
            sacc[jn][q] = v;
            mx[q >> 1] = fmaxf(mx[q >> 1], v);
        }
    #pragma unroll
    for (int o = 1; o < 4; o <<= 1) {
        mx[0] = fmaxf(mx[0], __shfl_xor_sync(0xffffffffu, mx[0], o));
        mx[1] = fmaxf(mx[1], __shfl_xor_sync(0xffffffffu, mx[1], o));
    }
    float sum[2] = {0.f, 0.f};
    #pragma unroll
    for (int jn = 0; jn < 8; jn++)
        #pragma unroll
        for (int q = 0; q < 4; q++) {
            float e = __expf(sacc[jn][q] - mx[q >> 1]);
            sacc[jn][q] = e;
            sum[q >> 1] += e;
        }
    #pragma unroll
    for (int o = 1; o < 4; o <<= 1) {
        sum[0] += __shfl_xor_sync(0xffffffffu, sum[0], o);
        sum[1] += __shfl_xor_sync(0xffffffffu, sum[1], o);
    }
    const float inv0 = 1.f / sum[0], inv1 = 1.f / sum[1];

    __syncthreads();

    #pragma unroll
    for (int jn = 0; jn < 8; jn++)
        #pragma unroll
        for (int q = 0; q < 4; q++) {
            int col = jn * 8 + 2 * t + (q & 1);
            int row = 16 * warp + g + ((q >= 2) ? 8 : 0);
            int pc = (col & 56) + (col & 3) * 2 + ((col >> 2) & 1);
            sS[row * 72 + pc] = tf32r(sacc[jn][q] * ((q >= 2) ? inv1 : inv0));
        }
    __syncwarp();

    float oacc[4][4];
    #pragma unroll
    for (int jn = 0; jn < 4; jn++)
        #pragma unroll
        for (int q = 0; q < 4; q++) oacc[jn][q] = 0.f;

    #pragma unroll
    for (int ks = 0; ks < 8; ks++) {
        const int k0 = ks * 8 + 2 * t;
        const float* ap = sS + (16 * warp + g) * 72 + k0;
        float2 a0 = *reinterpret_cast<const float2*>(ap);
        float2 a1 = *reinterpret_cast<const float2*>(ap + 8 * 72);
        #pragma unroll
        for (int jn = 0; jn < 4; jn++) {
            float2 bp = *reinterpret_cast<const float2*>(svT + (jn * 8 + g) * 72 + k0);
            mma_tf32(oacc[jn], a0.x, a1.x, a0.y, a1.y, bp.x, bp.y);
        }
    }

    // ---- write O (tf32, PERM-8 head-dim cols) into q-slot of g_qkv ----
    #pragma unroll
    for (int jn = 0; jn < 4; jn++)
        #pragma unroll
        for (int q = 0; q < 4; q++) {
            int row = 16 * warp + g + ((q >= 2) ? 8 : 0);
            int d = 2 * t + (q & 1);                     // dim within 8-group
            int pd = (d & 3) * 2 + (d >> 2);             // perm-8
            if (row < N_ACT)
                g_qkv[((size_t)b * N_ACT + row) * (3 * CDIM) + h * HD + jn * 8 + pd] =
                    tf32r(oacc[jn][q]);
        }
}

// ---------------------------------------------------------------------------
// Launch (static smem only; plain launches; graph-capturable)
// ---------------------------------------------------------------------------
extern "C" void kernel_launch(void* const* d_in, const int* in_sizes, int n_in,
                              void* d_out, int out_size) {
    const float *x = nullptr, *qkvw = nullptr, *qkvb = nullptr, *projw = nullptr, *projb = nullptr;
    for (int i = 0; i < n_in; i++) {
        int s = in_sizes[i];
        if (s == CDIM * 3 * CDIM)      qkvw = (const float*)d_in[i];
        else if (s == 3 * CDIM)        qkvb = (const float*)d_in[i];
        else if (s == CDIM * CDIM)     projw = (const float*)d_in[i];
        else if (s == CDIM)            projb = (const float*)d_in[i];
        else                           x = (const float*)d_in[i];
    }
    float* out = (float*)d_out;

    // pre-round + perm x; pre-transpose + round + perm weights
    kround<<<MROWS * CDIM / (256 * 8), 256>>>(x);
    ktranspose<<<dim3(3 * CDIM / 32, CDIM / 32), dim3(32, 32)>>>(qkvw, CDIM, 3 * CDIM, 0);
    ktranspose<<<dim3(CDIM / 32, CDIM / 32), dim3(32, 32)>>>(projw, CDIM, CDIM, 1);

    // QKV GEMM: g_qkv[122880 x 1536] = g_x @ qkv_w (+bias, q*scale, tf32)
    kgemm_ca<<<dim3(3 * CDIM / 128, MROWS / 256), 256>>>(qkvb, projb, out, 0);

    // attention per (window, head); O (tf32, perm-8) overwrites q-slot
    k_attn<<<dim3(BWIN, NHEAD), 128>>>();

    // proj GEMM: out[122880 x 512] = O @ proj_w + bias
    kgemm_ca<<<dim3(CDIM / 128, MROWS / 256), 256>>>(qkvb, projb, out, 1);
}

// round 15
// speedup vs baseline: 1.1332x; 1.1332x over previous
#include <cuda_runtime.h>
#include <cuda_bf16.h>
#include <cstdint>

// ---------------------------------------------------------------------------
// Problem constants (fixed instance: B=2048 windows, N_actual=60, C=512)
// ---------------------------------------------------------------------------
#define N_ACT    60
#define CDIM     512
#define NHEAD    16
#define HD       32
#define BWIN     2048
#define MROWS    (BWIN * N_ACT)          // 122880 = 960 * 128
#define SCALE_Q  0.1767766952966369f     // 32^-0.5

// ---------------------------------------------------------------------------
// Device scratch. K-dimension data (g_x cols, g_qkvT cols, g_projT cols,
// attn-O cols of g_qkv) stored PERM-8: per 8-col group order [0,4,1,5,2,6,3,7].
// ---------------------------------------------------------------------------
__device__ float g_qkvT[3 * CDIM * CDIM];            // [1536][512] W^T tf32, perm-8 cols
__device__ float g_projT[CDIM * CDIM];               // [512][512]  W^T tf32, perm-8 cols
__device__ float g_x[(size_t)MROWS * CDIM];          // [122880][512] x tf32, perm-8 cols
__device__ float g_qkv[(size_t)MROWS * 3 * CDIM];    // [122880][1536]

// ---------------------------------------------------------------------------
// Helpers
// ---------------------------------------------------------------------------
__device__ __forceinline__ float tf32r(float x) {
    float y;
    asm("cvt.rna.tf32.f32 %0, %1;" : "=f"(y) : "f"(x));
    return y;
}
__device__ __forceinline__ uint32_t f2u(float x) { return __float_as_uint(x); }

__device__ __forceinline__ void mma_tf32(float c[4],
                                         float a0, float a1, float a2, float a3,
                                         float b0, float b1) {
    asm volatile(
        "mma.sync.aligned.m16n8k8.row.col.f32.tf32.tf32.f32 "
        "{%0,%1,%2,%3}, {%4,%5,%6,%7}, {%8,%9}, {%0,%1,%2,%3};\n"
        : "+f"(c[0]), "+f"(c[1]), "+f"(c[2]), "+f"(c[3])
        : "r"(f2u(a0)), "r"(f2u(a1)), "r"(f2u(a2)), "r"(f2u(a3)),
          "r"(f2u(b0)), "r"(f2u(b1)));
}

__device__ __forceinline__ uint32_t smem_u32(const void* p) {
    uint32_t a;
    asm("{ .reg .u64 t; cvta.to.shared.u64 t, %1; cvt.u32.u64 %0, t; }"
        : "=r"(a) : "l"(p));
    return a;
}

__device__ __forceinline__ void cpa16(uint32_t smem_dst, const float* gsrc) {
    asm volatile("cp.async.cg.shared.global [%0], [%1], 16;"
                 :: "r"(smem_dst), "l"(gsrc));
}
#define CPA_COMMIT() asm volatile("cp.async.commit_group;" ::: "memory")
#define CPA_WAIT2()  asm volatile("cp.async.wait_group 2;" ::: "memory")

// ---------------------------------------------------------------------------
// Kernel: tf32-round x + perm-8 columns -> g_x. 8 floats per thread.
// ---------------------------------------------------------------------------
__global__ void kround(const float* __restrict__ src) {
    size_t i = ((size_t)blockIdx.x * 256 + threadIdx.x) * 8;
    float4 v0 = *reinterpret_cast<const float4*>(src + i);
    float4 v1 = *reinterpret_cast<const float4*>(src + i + 4);
    float4 o0 = make_float4(tf32r(v0.x), tf32r(v1.x), tf32r(v0.y), tf32r(v1.y));
    float4 o1 = make_float4(tf32r(v0.z), tf32r(v1.z), tf32r(v0.w), tf32r(v1.w));
    *reinterpret_cast<float4*>(g_x + i)     = o0;
    *reinterpret_cast<float4*>(g_x + i + 4) = o1;
}

// ---------------------------------------------------------------------------
// Kernel 0: transpose + tf32-round weights, perm-8 the k columns.
// ---------------------------------------------------------------------------
__global__ void ktranspose(const float* __restrict__ src, int R, int Ccols, int which) {
    __shared__ float tile[32][33];
    float* dst = which ? g_projT : g_qkvT;
    int cb = blockIdx.x * 32, rb = blockIdx.y * 32;
    tile[threadIdx.y][threadIdx.x] = src[(size_t)(rb + threadIdx.y) * Ccols + cb + threadIdx.x];
    __syncthreads();
    int tx = threadIdx.x;
    int px = (tx & 24) + (tx & 3) * 2 + ((tx >> 2) & 1);  // perm-8
    dst[(size_t)(cb + threadIdx.y) * R + rb + px] = tf32r(tile[threadIdx.x][threadIdx.y]);
}

// ---------------------------------------------------------------------------
// cp.async 4-stage pipelined tf32 GEMM.
// CTA tile 128x128, 128 threads (4 warps = 2m x 2n), warp tile 64x64.
// K-chunk 8, 64 chunks, 4 smem stages, wait_group(2) -> 3 loads in flight.
// Static smem: 4 stages x (128+128) x 8 x 4 = 32768 B. 2 CTAs/SM.
// Fragment loads LDS.64, conflict-free (perm-8 in gmem, 32B rows).
// mode 0: A=g_x (lda 512),  B=g_qkvT, bias=qkvb, C=g_qkv (ldc 1536)
// mode 1: A=g_qkv (lda 1536, attn-O perm-8+tf32), B=g_projT, bias=projb, C=out
// ---------------------------------------------------------------------------
#define KC 8
#define NSTG 4

__global__ __launch_bounds__(128, 2) void kgemm_ca(const float* __restrict__ qkvb,
                                                   const float* __restrict__ projb,
                                                   float* __restrict__ out,
                                                   int mode) {
    __shared__ __align__(16) float sA[NSTG][128 * KC];
    __shared__ __align__(16) float sB[NSTG][128 * KC];

    const float* Aptr = mode ? g_qkv : g_x;
    const int    lda  = mode ? (3 * CDIM) : CDIM;
    const float* Bw   = mode ? g_projT : g_qkvT;
    const float* bias = mode ? projb : qkvb;
    float*       Cp   = mode ? out : g_qkv;
    const int    ldc  = mode ? CDIM : (3 * CDIM);

    const int m0 = blockIdx.y * 128;
    const int n0 = blockIdx.x * 128;
    const int tid  = threadIdx.x;
    const int lane = tid & 31;
    const int warp = tid >> 5;
    const int g = lane >> 2, t = lane & 3;
    const int wm = warp & 1;       // 2 m-stripes of 64 rows
    const int wn = warp >> 1;      // 2 n-stripes of 64 cols

    // staging: thread loads row tid for A and row tid for B (32 B each)
    const float* aG = Aptr + (size_t)(m0 + tid) * lda;
    const float* bG = Bw + (size_t)(n0 + tid) * CDIM;
    const uint32_t aS = smem_u32(&sA[0][tid * KC]);
    const uint32_t bS = smem_u32(&sB[0][tid * KC]);
    const uint32_t stg = 128 * KC * 4;    // bytes per stage

    float acc[4][8][4];
    #pragma unroll
    for (int im = 0; im < 4; im++)
        #pragma unroll
        for (int jn = 0; jn < 8; jn++)
            #pragma unroll
            for (int q = 0; q < 4; q++) acc[im][jn][q] = 0.f;

    // prologue: stage chunks 0..2 into stages 0..2 (one commit group each)
    #pragma unroll
    for (int p = 0; p < NSTG - 1; p++) {
        const int ko = p * KC;
        cpa16(aS + p * stg, aG + ko);
        cpa16(aS + p * stg + 16, aG + ko + 4);
        cpa16(bS + p * stg, bG + ko);
        cpa16(bS + p * stg + 16, bG + ko + 4);
        CPA_COMMIT();
    }

    for (int kc = 0; kc < 64; kc++) {
        CPA_WAIT2();            // chunk kc resident (<=2 younger groups pending)
        __syncthreads();        // stage (kc-1)%4 free across all warps

        // issue chunk kc+3 into its stage; always commit to keep group count
        if (kc + NSTG - 1 < 64) {
            const uint32_t so = (uint32_t)((kc + NSTG - 1) & (NSTG - 1)) * stg;
            const int ko = (kc + NSTG - 1) * KC;
            cpa16(aS + so, aG + ko);
            cpa16(aS + so + 16, aG + ko + 4);
            cpa16(bS + so, bG + ko);
            cpa16(bS + so + 16, bG + ko + 4);
        }
        CPA_COMMIT();

        // compute chunk kc: 32 mmas per warp
        const int cur = kc & (NSTG - 1);
        const float* cA = &sA[cur][(wm * 64 + g) * KC + 2 * t];
        const float* cB = &sB[cur][(wn * 64 + g) * KC + 2 * t];
        float2 av[4][2];
        #pragma unroll
        for (int im = 0; im < 4; im++) {
            av[im][0] = *reinterpret_cast<const float2*>(cA + im * 16 * KC);
            av[im][1] = *reinterpret_cast<const float2*>(cA + im * 16 * KC + 8 * KC);
        }
        float2 bv[8];
        #pragma unroll
        for (int jn = 0; jn < 8; jn++)
            bv[jn] = *reinterpret_cast<const float2*>(cB + jn * 8 * KC);
        #pragma unroll
        for (int im = 0; im < 4; im++)
            #pragma unroll
            for (int jn = 0; jn < 8; jn++)
                mma_tf32(acc[im][jn],
                         av[im][0].x, av[im][1].x, av[im][0].y, av[im][1].y,
                         bv[jn].x, bv[jn].y);
    }

    // ---- epilogue: bias (+ q-scale / tf32 round for mode 0), float2 stores --
    #pragma unroll
    for (int im = 0; im < 4; im++) {
        #pragma unroll
        for (int jn = 0; jn < 8; jn++) {
            #pragma unroll
            for (int h = 0; h < 2; h++) {
                const int row = m0 + wm * 64 + im * 16 + g + h * 8;
                const int col = n0 + wn * 64 + jn * 8 + 2 * t;
                float v0 = acc[im][jn][2 * h + 0] + bias[col];
                float v1 = acc[im][jn][2 * h + 1] + bias[col + 1];
                if (mode == 0) {
                    if (col < CDIM) { v0 *= SCALE_Q; v1 *= SCALE_Q; }
                    v0 = tf32r(v0); v1 = tf32r(v1);
                }
                *reinterpret_cast<float2*>(Cp + (size_t)row * ldc + col) =
                    make_float2(v0, v1);
            }
        }
    }
}

// ---------------------------------------------------------------------------
// Attention kernel: one CTA per (window, head). 128 threads (4 warps).
// Reads q/k/v at LOGICAL cols; writes O tf32-rounded at PERM-8 cols.
// ---------------------------------------------------------------------------
__global__ __launch_bounds__(128) void k_attn() {
    __shared__ float sU[5120];
    __shared__ float svT[32 * 72];

    float* sq = sU;
    float* sk = sU + 2560;
    float* sS = sU;

    const int b = blockIdx.x;
    const int h = blockIdx.y;
    const int tid  = threadIdx.x;
    const int lane = tid & 31;
    const int warp = tid >> 5;
    const int g = lane >> 2, t = lane & 3;

    const float* qb = g_qkv + (size_t)b * N_ACT * (3 * CDIM) + h * HD;
    const float* kb = qb + CDIM;
    const float* vb = qb + 2 * CDIM;

    for (int i = tid; i < 64 * 8; i += 128) {
        int r = i >> 3, c4 = i & 7, cb = c4 * 4;
        float4 vq, vk, vv;
        if (r < N_ACT) {
            vq = *reinterpret_cast<const float4*>(qb + (size_t)r * (3 * CDIM) + cb);
            vk = *reinterpret_cast<const float4*>(kb + (size_t)r * (3 * CDIM) + cb);
            vv = *reinterpret_cast<const float4*>(vb + (size_t)r * (3 * CDIM) + cb);
        } else {
            vq = vk = vv = make_float4(0.f, 0.f, 0.f, 0.f);
        }
        int base = r * 40 + (cb & 24) + ((cb >> 2) & 1);
        sq[base + 0] = vq.x; sq[base + 2] = vq.y; sq[base + 4] = vq.z; sq[base + 6] = vq.w;
        sk[base + 0] = vk.x; sk[base + 2] = vk.y; sk[base + 4] = vk.z; sk[base + 6] = vk.w;
        int pr = (r & 56) + (r & 3) * 2 + ((r >> 2) & 1);
        svT[(cb + 0) * 72 + pr] = vv.x;
        svT[(cb + 1) * 72 + pr] = vv.y;
        svT[(cb + 2) * 72 + pr] = vv.z;
        svT[(cb + 3) * 72 + pr] = vv.w;
    }
    __syncthreads();

    float sacc[8][4];
    #pragma unroll
    for (int jn = 0; jn < 8; jn++)
        #pragma unroll
        for (int q = 0; q < 4; q++) sacc[jn][q] = 0.f;

    #pragma unroll
    for (int ks = 0; ks < 4; ks++) {
        const int k0 = ks * 8 + 2 * t;
        const float* ap = sq + (16 * warp + g) * 40 + k0;
        float2 a0 = *reinterpret_cast<const float2*>(ap);
        float2 a1 = *reinterpret_cast<const float2*>(ap + 8 * 40);
        #pragma unroll
        for (int jn = 0; jn < 8; jn++) {
            float2 bp = *reinterpret_cast<const float2*>(sk + (jn * 8 + g) * 40 + k0);
            mma_tf32(sacc[jn], a0.x, a1.x, a0.y, a1.y, bp.x, bp.y);
        }
    }

    float mx[2] = {-1e30f, -1e30f};
    #pragma unroll
    for (int jn = 0; jn < 8; jn++)
        #pragma unroll
        for (int q = 0; q < 4; q++) {
            int col = jn * 8 + 2 * t + (q & 1);
            float v = sacc[jn][q] + (col >= N_ACT ? -1e9f : 0.f);
            sacc[jn][q] = v;
            mx[q >> 1] = fmaxf(mx[q >> 1], v);
        }
    #pragma unroll
    for (int o = 1; o < 4; o <<= 1) {
        mx[0] = fmaxf(mx[0], __shfl_xor_sync(0xffffffffu, mx[0], o));
        mx[1] = fmaxf(mx[1], __shfl_xor_sync(0xffffffffu, mx[1], o));
    }
    float sum[2] = {0.f, 0.f};
    #pragma unroll
    for (int jn = 0; jn < 8; jn++)
        #pragma unroll
        for (int q = 0; q < 4; q++) {
            float e = __expf(sacc[jn][q] - mx[q >> 1]);
            sacc[jn][q] = e;
            sum[q >> 1] += e;
        }
    #pragma unroll
    for (int o = 1; o < 4; o <<= 1) {
        sum[0] += __shfl_xor_sync(0xffffffffu, sum[0], o);
        sum[1] += __shfl_xor_sync(0xffffffffu, sum[1], o);
    }
    const float inv0 = 1.f / sum[0], inv1 = 1.f / sum[1];

    __syncthreads();

    #pragma unroll
    for (int jn = 0; jn < 8; jn++)
        #pragma unroll
        for (int q = 0; q < 4; q++) {
            int col = jn * 8 + 2 * t + (q & 1);
            int row = 16 * warp + g + ((q >= 2) ? 8 : 0);
            int pc = (col & 56) + (col & 3) * 2 + ((col >> 2) & 1);
            sS[row * 72 + pc] = tf32r(sacc[jn][q] * ((q >= 2) ? inv1 : inv0));
        }
    __syncwarp();

    float oacc[4][4];
    #pragma unroll
    for (int jn = 0; jn < 4; jn++)
        #pragma unroll
        for (int q = 0; q < 4; q++) oacc[jn][q] = 0.f;

    #pragma unroll
    for (int ks = 0; ks < 8; ks++) {
        const int k0 = ks * 8 + 2 * t;
        const float* ap = sS + (16 * warp + g) * 72 + k0;
        float2 a0 = *reinterpret_cast<const float2*>(ap);
        float2 a1 = *reinterpret_cast<const float2*>(ap + 8 * 72);
        #pragma unroll
        for (int jn = 0; jn < 4; jn++) {
            float2 bp = *reinterpret_cast<const float2*>(svT + (jn * 8 + g) * 72 + k0);
            mma_tf32(oacc[jn], a0.x, a1.x, a0.y, a1.y, bp.x, bp.y);
        }
    }

    // write O (tf32, PERM-8 head-dim cols) into q-slot of g_qkv
    #pragma unroll
    for (int jn = 0; jn < 4; jn++)
        #pragma unroll
        for (int q = 0; q < 4; q++) {
            int row = 16 * warp + g + ((q >= 2) ? 8 : 0);
            int d = 2 * t + (q & 1);
            int pd = (d & 3) * 2 + (d >> 2);             // perm-8
            if (row < N_ACT)
                g_qkv[((size_t)b * N_ACT + row) * (3 * CDIM) + h * HD + jn * 8 + pd] =
                    tf32r(oacc[jn][q]);
        }
}

// ---------------------------------------------------------------------------
// Launch (static smem only; plain launches; graph-capturable)
// ---------------------------------------------------------------------------
extern "C" void kernel_launch(void* const* d_in, const int* in_sizes, int n_in,
                              void* d_out, int out_size) {
    const float *x = nullptr, *qkvw = nullptr, *qkvb = nullptr, *projw = nullptr, *projb = nullptr;
    for (int i = 0; i < n_in; i++) {
        int s = in_sizes[i];
        if (s == CDIM * 3 * CDIM)      qkvw = (const float*)d_in[i];
        else if (s == 3 * CDIM)        qkvb = (const float*)d_in[i];
        else if (s == CDIM * CDIM)     projw = (const float*)d_in[i];
        else if (s == CDIM)            projb = (const float*)d_in[i];
        else                           x = (const float*)d_in[i];
    }
    float* out = (float*)d_out;

    // pre-round + perm x; pre-transpose + round + perm weights
    kround<<<MROWS * CDIM / (256 * 8), 256>>>(x);
    ktranspose<<<dim3(3 * CDIM / 32, CDIM / 32), dim3(32, 32)>>>(qkvw, CDIM, 3 * CDIM, 0);
    ktranspose<<<dim3(CDIM / 32, CDIM / 32), dim3(32, 32)>>>(projw, CDIM, CDIM, 1);

    // QKV GEMM: g_qkv[122880 x 1536] = g_x @ qkv_w (+bias, q*scale, tf32)
    kgemm_ca<<<dim3(3 * CDIM / 128, MROWS / 128), 128>>>(qkvb, projb, out, 0);

    // attention per (window, head); O (tf32, perm-8) overwrites q-slot
    k_attn<<<dim3(BWIN, NHEAD), 128>>>();

    // proj GEMM: out[122880 x 512] = O @ proj_w + bias
    kgemm_ca<<<dim3(CDIM / 128, MROWS / 128), 128>>>(qkvb, projb, out, 1);
}

// round 16
// speedup vs baseline: 1.2646x; 1.1159x over previous
#include <cuda_runtime.h>
#include <cuda_bf16.h>
#include <cstdint>

// ---------------------------------------------------------------------------
// Problem constants (fixed instance: B=2048 windows, N_actual=60, C=512)
// ---------------------------------------------------------------------------
#define N_ACT    60
#define CDIM     512
#define NHEAD    16
#define HD       32
#define BWIN     2048
#define MROWS    (BWIN * N_ACT)          // 122880 = 960 * 128
#define SCALE_Q  0.1767766952966369f     // 32^-0.5

// ---------------------------------------------------------------------------
// Device scratch. K-dimension data (g_x cols, g_qkvT cols, g_projT cols,
// attn-O cols of g_qkv) stored PERM-8: per 8-col group order [0,4,1,5,2,6,3,7].
// ---------------------------------------------------------------------------
__device__ float g_qkvT[3 * CDIM * CDIM];            // [1536][512] W^T tf32, perm-8 cols
__device__ float g_projT[CDIM * CDIM];               // [512][512]  W^T tf32, perm-8 cols
__device__ float g_x[(size_t)MROWS * CDIM];          // [122880][512] x tf32, perm-8 cols
__device__ float g_qkv[(size_t)MROWS * 3 * CDIM];    // [122880][1536]

// ---------------------------------------------------------------------------
// Helpers
// ---------------------------------------------------------------------------
__device__ __forceinline__ float tf32r(float x) {
    float y;
    asm("cvt.rna.tf32.f32 %0, %1;" : "=f"(y) : "f"(x));
    return y;
}
__device__ __forceinline__ uint32_t f2u(float x) { return __float_as_uint(x); }

__device__ __forceinline__ void mma_tf32(float c[4],
                                         float a0, float a1, float a2, float a3,
                                         float b0, float b1) {
    asm volatile(
        "mma.sync.aligned.m16n8k8.row.col.f32.tf32.tf32.f32 "
        "{%0,%1,%2,%3}, {%4,%5,%6,%7}, {%8,%9}, {%0,%1,%2,%3};\n"
        : "+f"(c[0]), "+f"(c[1]), "+f"(c[2]), "+f"(c[3])
        : "r"(f2u(a0)), "r"(f2u(a1)), "r"(f2u(a2)), "r"(f2u(a3)),
          "r"(f2u(b0)), "r"(f2u(b1)));
}

__device__ __forceinline__ uint32_t smem_u32(const void* p) {
    uint32_t a;
    asm("{ .reg .u64 t; cvta.to.shared.u64 t, %1; cvt.u32.u64 %0, t; }"
        : "=r"(a) : "l"(p));
    return a;
}

__device__ __forceinline__ void cpa16(uint32_t smem_dst, const float* gsrc) {
    asm volatile("cp.async.cg.shared.global [%0], [%1], 16;"
                 :: "r"(smem_dst), "l"(gsrc));
}
#define CPA_COMMIT() asm volatile("cp.async.commit_group;" ::: "memory")
#define CPA_WAIT1()  asm volatile("cp.async.wait_group 1;" ::: "memory")

// ---------------------------------------------------------------------------
// Kernel: tf32-round x + perm-8 columns -> g_x. 8 floats per thread.
// ---------------------------------------------------------------------------
__global__ void kround(const float* __restrict__ src) {
    size_t i = ((size_t)blockIdx.x * 256 + threadIdx.x) * 8;
    float4 v0 = *reinterpret_cast<const float4*>(src + i);
    float4 v1 = *reinterpret_cast<const float4*>(src + i + 4);
    float4 o0 = make_float4(tf32r(v0.x), tf32r(v1.x), tf32r(v0.y), tf32r(v1.y));
    float4 o1 = make_float4(tf32r(v0.z), tf32r(v1.z), tf32r(v0.w), tf32r(v1.w));
    *reinterpret_cast<float4*>(g_x + i)     = o0;
    *reinterpret_cast<float4*>(g_x + i + 4) = o1;
}

// ---------------------------------------------------------------------------
// Kernel 0: transpose + tf32-round weights, perm-8 the k columns.
// ---------------------------------------------------------------------------
__global__ void ktranspose(const float* __restrict__ src, int R, int Ccols, int which) {
    __shared__ float tile[32][33];
    float* dst = which ? g_projT : g_qkvT;
    int cb = blockIdx.x * 32, rb = blockIdx.y * 32;
    tile[threadIdx.y][threadIdx.x] = src[(size_t)(rb + threadIdx.y) * Ccols + cb + threadIdx.x];
    __syncthreads();
    int tx = threadIdx.x;
    int px = (tx & 24) + (tx & 3) * 2 + ((tx >> 2) & 1);  // perm-8
    dst[(size_t)(cb + threadIdx.y) * R + rb + px] = tf32r(tile[threadIdx.x][threadIdx.y]);
}

// ---------------------------------------------------------------------------
// cp.async 3-stage pipelined tf32 GEMM.
// CTA tile 128x128, 256 threads (8 warps = 4m x 2n), warp tile 32x64
// (64-reg accumulator -> 2 CTAs/SM = 16 warps).
// Chunk = 16 k (two 8-k sub-blocks, 32B rows, conflict-free LDS.64).
// 3 smem stages x 16 KB = 49152 B static. wait_group(1): one chunk-load
// always in flight, covered by ~32 mmas/warp of compute.
// Stage layout (floats): [A_sub0 1024][A_sub1 1024][B_sub0 1024][B_sub1 1024]
// mode 0: A=g_x (lda 512),  B=g_qkvT, bias=qkvb, C=g_qkv (ldc 1536)
// mode 1: A=g_qkv (lda 1536, attn-O perm-8+tf32), B=g_projT, bias=projb, C=out
// ---------------------------------------------------------------------------
#define NSTG 3
#define STGF 4096          // floats per stage

__global__ __launch_bounds__(256, 2) void kgemm_ca(const float* __restrict__ qkvb,
                                                   const float* __restrict__ projb,
                                                   float* __restrict__ out,
                                                   int mode) {
    __shared__ __align__(16) float smP[NSTG][STGF];   // 49152 B

    const float* Aptr = mode ? g_qkv : g_x;
    const int    lda  = mode ? (3 * CDIM) : CDIM;
    const float* Bw   = mode ? g_projT : g_qkvT;
    const float* bias = mode ? projb : qkvb;
    float*       Cp   = mode ? out : g_qkv;
    const int    ldc  = mode ? CDIM : (3 * CDIM);

    const int m0 = blockIdx.y * 128;
    const int n0 = blockIdx.x * 128;
    const int tid  = threadIdx.x;
    const int lane = tid & 31;
    const int warp = tid >> 5;
    const int g = lane >> 2, t = lane & 3;
    const int wm = warp & 3;       // 4 m-stripes of 32 rows
    const int wn = warp >> 2;      // 2 n-stripes of 64 cols

    // staging: thread -> row r = tid>>1 (0..127), 16B half h = tid&1.
    // Per stage it loads: A sub0/sub1 and B sub0/sub1 (4 x cp.async 16B).
    const int sr = tid >> 1;
    const int sh = tid & 1;
    const float* aG = Aptr + (size_t)(m0 + sr) * lda + sh * 4;
    const float* bG = Bw + (size_t)(n0 + sr) * CDIM + sh * 4;
    const uint32_t s0 = smem_u32(&smP[0][0]) + (uint32_t)(sr * 32 + sh * 16);
    const uint32_t STGB = STGF * 4;          // stage bytes (16384)

    float acc[2][8][4];
    #pragma unroll
    for (int im = 0; im < 2; im++)
        #pragma unroll
        for (int jn = 0; jn < 8; jn++)
            #pragma unroll
            for (int q = 0; q < 4; q++) acc[im][jn][q] = 0.f;

    // prologue: stage chunks 0 and 1 into stages 0,1
    #pragma unroll
    for (int p = 0; p < 2; p++) {
        const int kf = p * 16;               // chunk start (floats, perm-8 space)
        cpa16(s0 + p * STGB,          aG + kf);          // A sub0
        cpa16(s0 + p * STGB + 4096,   aG + kf + 8);      // A sub1
        cpa16(s0 + p * STGB + 8192,   bG + kf);          // B sub0
        cpa16(s0 + p * STGB + 12288,  bG + kf + 8);      // B sub1
        CPA_COMMIT();
    }

    for (int kc = 0; kc < 32; kc++) {
        CPA_WAIT1();            // chunk kc resident (kc+1 may still fly)
        __syncthreads();        // all warps done reading stage (kc-1)%3

        // issue chunk kc+2 into stage (kc+2)%3 (== (kc-1)%3, just freed)
        if (kc + 2 < 32) {
            const uint32_t sb = (uint32_t)((kc + 2) % NSTG) * STGB;
            const int kf = (kc + 2) * 16;
            cpa16(s0 + sb,         aG + kf);
            cpa16(s0 + sb + 4096,  aG + kf + 8);
            cpa16(s0 + sb + 8192,  bG + kf);
            cpa16(s0 + sb + 12288, bG + kf + 8);
        }
        CPA_COMMIT();

        // compute chunk kc: 2 sub-blocks x 16 mmas per warp
        const float* stg = &smP[kc % NSTG][0];
        #pragma unroll
        for (int s = 0; s < 2; s++) {
            const float* cA = stg + s * 1024 + (wm * 32 + g) * 8 + 2 * t;
            const float* cB = stg + 2048 + s * 1024 + (wn * 64 + g) * 8 + 2 * t;
            float2 av[2][2];
            #pragma unroll
            for (int im = 0; im < 2; im++) {
                av[im][0] = *reinterpret_cast<const float2*>(cA + im * 16 * 8);
                av[im][1] = *reinterpret_cast<const float2*>(cA + im * 16 * 8 + 64);
            }
            float2 bv[8];
            #pragma unroll
            for (int jn = 0; jn < 8; jn++)
                bv[jn] = *reinterpret_cast<const float2*>(cB + jn * 64);
            #pragma unroll
            for (int im = 0; im < 2; im++)
                #pragma unroll
                for (int jn = 0; jn < 8; jn++)
                    mma_tf32(acc[im][jn],
                             av[im][0].x, av[im][1].x, av[im][0].y, av[im][1].y,
                             bv[jn].x, bv[jn].y);
        }
    }

    // ---- epilogue: bias (+ q-scale / tf32 round for mode 0), float2 stores --
    #pragma unroll
    for (int im = 0; im < 2; im++) {
        #pragma unroll
        for (int jn = 0; jn < 8; jn++) {
            #pragma unroll
            for (int h = 0; h < 2; h++) {
                const int row = m0 + wm * 32 + im * 16 + g + h * 8;
                const int col = n0 + wn * 64 + jn * 8 + 2 * t;
                float v0 = acc[im][jn][2 * h + 0] + bias[col];
                float v1 = acc[im][jn][2 * h + 1] + bias[col + 1];
                if (mode == 0) {
                    if (col < CDIM) { v0 *= SCALE_Q; v1 *= SCALE_Q; }
                    v0 = tf32r(v0); v1 = tf32r(v1);
                }
                *reinterpret_cast<float2*>(Cp + (size_t)row * ldc + col) =
                    make_float2(v0, v1);
            }
        }
    }
}

// ---------------------------------------------------------------------------
// Attention kernel: one CTA per (window, head). 128 threads (4 warps).
// Reads q/k/v at LOGICAL cols; writes O tf32-rounded at PERM-8 cols.
// ---------------------------------------------------------------------------
__global__ __launch_bounds__(128) void k_attn() {
    __shared__ float sU[5120];
    __shared__ float svT[32 * 72];

    float* sq = sU;
    float* sk = sU + 2560;
    float* sS = sU;

    const int b = blockIdx.x;
    const int h = blockIdx.y;
    const int tid  = threadIdx.x;
    const int lane = tid & 31;
    const int warp = tid >> 5;
    const int g = lane >> 2, t = lane & 3;

    const float* qb = g_qkv + (size_t)b * N_ACT * (3 * CDIM) + h * HD;
    const float* kb = qb + CDIM;
    const float* vb = qb + 2 * CDIM;

    for (int i = tid; i < 64 * 8; i += 128) {
        int r = i >> 3, c4 = i & 7, cb = c4 * 4;
        float4 vq, vk, vv;
        if (r < N_ACT) {
            vq = *reinterpret_cast<const float4*>(qb + (size_t)r * (3 * CDIM) + cb);
            vk = *reinterpret_cast<const float4*>(kb + (size_t)r * (3 * CDIM) + cb);
            vv = *reinterpret_cast<const float4*>(vb + (size_t)r * (3 * CDIM) + cb);
        } else {
            vq = vk = vv = make_float4(0.f, 0.f, 0.f, 0.f);
        }
        int base = r * 40 + (cb & 24) + ((cb >> 2) & 1);
        sq[base + 0] = vq.x; sq[base + 2] = vq.y; sq[base + 4] = vq.z; sq[base + 6] = vq.w;
        sk[base + 0] = vk.x; sk[base + 2] = vk.y; sk[base + 4] = vk.z; sk[base + 6] = vk.w;
        int pr = (r & 56) + (r & 3) * 2 + ((r >> 2) & 1);
        svT[(cb + 0) * 72 + pr] = vv.x;
        svT[(cb + 1) * 72 + pr] = vv.y;
        svT[(cb + 2) * 72 + pr] = vv.z;
        svT[(cb + 3) * 72 + pr] = vv.w;
    }
    __syncthreads();

    float sacc[8][4];
    #pragma unroll
    for (int jn = 0; jn < 8; jn++)
        #pragma unroll
        for (int q = 0; q < 4; q++) sacc[jn][q] = 0.f;

    #pragma unroll
    for (int ks = 0; ks < 4; ks++) {
        const int k0 = ks * 8 + 2 * t;
        const float* ap = sq + (16 * warp + g) * 40 + k0;
        float2 a0 = *reinterpret_cast<const float2*>(ap);
        float2 a1 = *reinterpret_cast<const float2*>(ap + 8 * 40);
        #pragma unroll
        for (int jn = 0; jn < 8; jn++) {
            float2 bp = *reinterpret_cast<const float2*>(sk + (jn * 8 + g) * 40 + k0);
            mma_tf32(sacc[jn], a0.x, a1.x, a0.y, a1.y, bp.x, bp.y);
        }
    }

    float mx[2] = {-1e30f, -1e30f};
    #pragma unroll
    for (int jn = 0; jn < 8; jn++)
        #pragma unroll
        for (int q = 0; q < 4; q++) {
            int col = jn * 8 + 2 * t + (q & 1);
            float v = sacc[jn][q] + (col >= N_ACT ? -1e9f : 0.f);
            sacc[jn][q] = v;
            mx[q >> 1] = fmaxf(mx[q >> 1], v);
        }
    #pragma unroll
    for (int o = 1; o < 4; o <<= 1) {
        mx[0] = fmaxf(mx[0], __shfl_xor_sync(0xffffffffu, mx[0], o));
        mx[1] = fmaxf(mx[1], __shfl_xor_sync(0xffffffffu, mx[1], o));
    }
    float sum[2] = {0.f, 0.f};
    #pragma unroll
    for (int jn = 0; jn < 8; jn++)
        #pragma unroll
        for (int q = 0; q < 4; q++) {
            float e = __expf(sacc[jn][q] - mx[q >> 1]);
            sacc[jn][q] = e;
            sum[q >> 1] += e;
        }
    #pragma unroll
    for (int o = 1; o < 4; o <<= 1) {
        sum[0] += __shfl_xor_sync(0xffffffffu, sum[0], o);
        sum[1] += __shfl_xor_sync(0xffffffffu, sum[1], o);
    }
    const float inv0 = 1.f / sum[0], inv1 = 1.f / sum[1];

    __syncthreads();

    #pragma unroll
    for (int jn = 0; jn < 8; jn++)
        #pragma unroll
        for (int q = 0; q < 4; q++) {
            int col = jn * 8 + 2 * t + (q & 1);
            int row = 16 * warp + g + ((q >= 2) ? 8 : 0);
            int pc = (col & 56) + (col & 3) * 2 + ((col >> 2) & 1);
            sS[row * 72 + pc] = tf32r(sacc[jn][q] * ((q >= 2) ? inv1 : inv0));
        }
    __syncwarp();

    float oacc[4][4];
    #pragma unroll
    for (int jn = 0; jn < 4; jn++)
        #pragma unroll
        for (int q = 0; q < 4; q++) oacc[jn][q] = 0.f;

    #pragma unroll
    for (int ks = 0; ks < 8; ks++) {
        const int k0 = ks * 8 + 2 * t;
        const float* ap = sS + (16 * warp + g) * 72 + k0;
        float2 a0 = *reinterpret_cast<const float2*>(ap);
        float2 a1 = *reinterpret_cast<const float2*>(ap + 8 * 72);
        #pragma unroll
        for (int jn = 0; jn < 4; jn++) {
            float2 bp = *reinterpret_cast<const float2*>(svT + (jn * 8 + g) * 72 + k0);
            mma_tf32(oacc[jn], a0.x, a1.x, a0.y, a1.y, bp.x, bp.y);
        }
    }

    // write O (tf32, PERM-8 head-dim cols) into q-slot of g_qkv
    #pragma unroll
    for (int jn = 0; jn < 4; jn++)
        #pragma unroll
        for (int q = 0; q < 4; q++) {
            int row = 16 * warp + g + ((q >= 2) ? 8 : 0);
            int d = 2 * t + (q & 1);
            int pd = (d & 3) * 2 + (d >> 2);             // perm-8
            if (row < N_ACT)
                g_qkv[((size_t)b * N_ACT + row) * (3 * CDIM) + h * HD + jn * 8 + pd] =
                    tf32r(oacc[jn][q]);
        }
}

// ---------------------------------------------------------------------------
// Launch (static smem only; plain launches; graph-capturable)
// ---------------------------------------------------------------------------
extern "C" void kernel_launch(void* const* d_in, const int* in_sizes, int n_in,
                              void* d_out, int out_size) {
    const float *x = nullptr, *qkvw = nullptr, *qkvb = nullptr, *projw = nullptr, *projb = nullptr;
    for (int i = 0; i < n_in; i++) {
        int s = in_sizes[i];
        if (s == CDIM * 3 * CDIM)      qkvw = (const float*)d_in[i];
        else if (s == 3 * CDIM)        qkvb = (const float*)d_in[i];
        else if (s == CDIM * CDIM)     projw = (const float*)d_in[i];
        else if (s == CDIM)            projb = (const float*)d_in[i];
        else                           x = (const float*)d_in[i];
    }
    float* out = (float*)d_out;

    // pre-round + perm x; pre-transpose + round + perm weights
    kround<<<MROWS * CDIM / (256 * 8), 256>>>(x);
    ktranspose<<<dim3(3 * CDIM / 32, CDIM / 32), dim3(32, 32)>>>(qkvw, CDIM, 3 * CDIM, 0);
    ktranspose<<<dim3(CDIM / 32, CDIM / 32), dim3(32, 32)>>>(projw, CDIM, CDIM, 1);

    // QKV GEMM: g_qkv[122880 x 1536] = g_x @ qkv_w (+bias, q*scale, tf32)
    kgemm_ca<<<dim3(3 * CDIM / 128, MROWS / 128), 256>>>(qkvb, projb, out, 0);

    // attention per (window, head); O (tf32, perm-8) overwrites q-slot
    k_attn<<<dim3(BWIN, NHEAD), 128>>>();

    // proj GEMM: out[122880 x 512] = O @ proj_w + bias
    kgemm_ca<<<dim3(CDIM / 128, MROWS / 128), 256>>>(qkvb, projb, out, 1);
}